// round 3
// baseline (speedup 1.0000x reference)
#include <cuda_runtime.h>
#include <cuda_fp16.h>
#include <math.h>

// ---------------------------------------------------------------------------
// Problem constants
//   D=10000 EMB=1000 HID=1000 VIS=2688 MIX=1000 HMIX=1005 T=8 H=16 W=16
//   mRNN sequence length = H*W*T = 2048, order s = hw*8 + t
// ---------------------------------------------------------------------------

#define NB_RECUR 144          // persistent blocks (<= 148 SMs, co-resident)
#define UPB      7            // hidden units per block (144*7 = 1008 >= 1005)

// ------------------------------ scratch (device globals; no allocs) --------
__device__ __align__(16) float g_le[8 * 1000];
__device__ __align__(16) float g_prelang[8 * 4000];
__device__ __align__(16) float g_h1l[8 * 1024];
__device__ __align__(16) float g_lo[8 * 1024];
__device__ __align__(16) float g_filt[8 * 2690];
__device__ __align__(16) float g_vxT[256 * 2720];
__device__ __align__(16) float g_p[8 * 256];
__device__ __align__(16) float g_ppart[64 * 256];
__device__ __align__(16) float g_lelo[8 * 2000];
__device__ __align__(16) float g_A[256 * 1000];
__device__ __align__(16) float g_Bt[8 * 1000];
__device__ __align__(16) float g_xseq[2048 * 1024];
__device__ __align__(16) float g_prem[2048 * 4020];
__device__ __align__(16) float g_hA[2048 * 1024];
__device__ __align__(16) float g_hB[2048 * 1024];
__device__ __align__(16) float g_hbuf[2][1024];   // double-buffered hidden state
__device__ __align__(16) float g_zero[4096];      // zero-initialized
__device__ unsigned g_bar_count;                  // zero-initialized
__device__ unsigned g_bar_gen;

// ------------------------------ helpers ------------------------------------
__device__ __forceinline__ float sigf(float x) { return 1.f / (1.f + expf(-x)); }

__device__ __forceinline__ void grid_barrier(unsigned nb) {
    __syncthreads();
    __threadfence();
    if (threadIdx.x == 0) {
        unsigned g = *((volatile unsigned*)&g_bar_gen);
        unsigned old = atomicInc(&g_bar_count, nb - 1u);
        if (old == nb - 1u) {
            *((volatile unsigned*)&g_bar_gen) = g + 1u;
        } else {
            while (*((volatile unsigned*)&g_bar_gen) == g) { }
        }
    }
    __syncthreads();
    __threadfence();
}

__device__ __forceinline__ unsigned pack_h2(float a, float b) {
    __half2 h = __floats2half2_rn(a, b);
    return *reinterpret_cast<unsigned*>(&h);
}

// ------------------------------ small kernels -------------------------------

// le[t, j] = emb_table[lang[t], j]
__global__ void k_embed(const float* __restrict__ emb, const int* __restrict__ lang,
                        float* __restrict__ le) {
    int t = blockIdx.x;
    const float* row = emb + (size_t)lang[t] * 1000;
    for (int j = threadIdx.x; j < 1000; j += blockDim.x)
        le[t * 1000 + j] = __ldg(&row[j]);
}

// visxyT[hw, c] = vis_xy[c, hw]  (transposed layout, stride 2720)
__global__ void k_visxyT(const float* __restrict__ vis, float* __restrict__ out) {
    int c = blockIdx.x;          // 0..2689
    int hw = threadIdx.x;        // 0..255
    float v;
    if (c < 2688)       v = __ldg(&vis[(size_t)c * 256 + hw]);
    else if (c == 2688) v = -1.f + 2.f * (float)(hw & 15) / 15.f;   // xg = xs[w]
    else                v = -1.f + 2.f * (float)(hw >> 4) / 15.f;   // yg = ys[h]
    out[(size_t)hw * 2720 + c] = v;
}

// partial p: part[(chunk*8+t), hw] = sum_{c in chunk} filt[t,c]*vis[c,hw]
__global__ void k_p_part(const float* __restrict__ filt, const float* __restrict__ vis,
                         float* __restrict__ part) {
    __shared__ float fs[336];
    int t = blockIdx.x, chunk = blockIdx.y;
    int c0 = chunk * 336;                         // 8*336 = 2688
    for (int c = threadIdx.x; c < 336; c += 256) fs[c] = filt[t * 2690 + c0 + c];
    __syncthreads();
    int hw = threadIdx.x;
    float acc = 0.f;
#pragma unroll 4
    for (int c = 0; c < 336; c++) acc += fs[c] * __ldg(&vis[(size_t)(c0 + c) * 256 + hw]);
    part[(chunk * 8 + t) * 256 + hw] = acc;
}

// p[t,hw] = sum_chunk part + filt[t,2688]*xg + filt[t,2689]*yg
__global__ void k_p_reduce(const float* __restrict__ part, const float* __restrict__ filt,
                           float* __restrict__ p) {
    int t = blockIdx.x, hw = threadIdx.x;
    float acc = 0.f;
#pragma unroll
    for (int ch = 0; ch < 8; ch++) acc += part[(ch * 8 + t) * 256 + hw];
    float xg = -1.f + 2.f * (float)(hw & 15) / 15.f;
    float yg = -1.f + 2.f * (float)(hw >> 4) / 15.f;
    acc += filt[t * 2690 + 2688] * xg + filt[t * 2690 + 2689] * yg;
    p[t * 256 + hw] = acc;
}

// lelo[t, j] : concat(le[t], lo[t])
__global__ void k_lelo(const float* __restrict__ le, const float* __restrict__ lo,
                       float* __restrict__ lelo) {
    int t = blockIdx.x;
    for (int j = threadIdx.x; j < 2000; j += blockDim.x)
        lelo[t * 2000 + j] = (j < 1000) ? le[t * 1000 + j] : lo[t * 1024 + (j - 1000)];
}

// xseq[s, m] = A[hw, m] + Bt[t, m] + cc_W[m, 4690] * p[t, hw],  s = hw*8 + t
__global__ void k_xseq(const float* __restrict__ A, const float* __restrict__ Bt,
                       const float* __restrict__ p, const float* __restrict__ ccW,
                       float* __restrict__ xseq) {
    int s = blockIdx.x;
    int hw = s >> 3, t = s & 7;
    float pv = p[t * 256 + hw];
    for (int m = threadIdx.x; m < 1000; m += blockDim.x)
        xseq[(size_t)s * 1024 + m] =
            A[hw * 1000 + m] + Bt[t * 1000 + m] + __ldg(&ccW[(size_t)m * 4691 + 4690]) * pv;
}

// out[idx] = oc_b + sum_c oc_W[c] * h3[(1792+idx), c]
__global__ void k_final(const float* __restrict__ h3, const float* __restrict__ ocW,
                        const float* __restrict__ ocb, float* __restrict__ out) {
    __shared__ float red[256];
    int idx = blockIdx.x;
    const float* hr = h3 + (size_t)(1792 + idx) * 1024;
    float acc = 0.f;
    for (int c = threadIdx.x; c < 1005; c += 256) acc += hr[c] * __ldg(&ocW[c]);
    red[threadIdx.x] = acc;
    __syncthreads();
    for (int off = 128; off; off >>= 1) {
        if (threadIdx.x < off) red[threadIdx.x] += red[threadIdx.x + off];
        __syncthreads();
    }
    if (threadIdx.x == 0) out[idx] = red[0] + ocb[0];
}

// ------------------------- 64x64 tiled GEMM (small S) ------------------------
// out[s, r] = act( sum_k W[r, k] * X[s, k] + b1[r] + b2[r] )
__global__ void k_gemm64(const float* __restrict__ X, int xs,
                         const float* __restrict__ W, int ws,
                         const float* __restrict__ b1, const float* __restrict__ b2,
                         float* __restrict__ out, int os,
                         int S, int R, int K, int act) {
    __shared__ float Wt[32][68];
    __shared__ float Xt[32][68];
    const int tid = threadIdx.x;
    const int tx = tid & 15, ty = tid >> 4;
    const int rblk = blockIdx.x << 6, sblk = blockIdx.y << 6;
    const int r0 = rblk + (tx << 2), s0 = sblk + (ty << 2);
    float acc[4][4];
#pragma unroll
    for (int j = 0; j < 4; j++)
#pragma unroll
        for (int i = 0; i < 4; i++) acc[j][i] = 0.f;

    for (int k0 = 0; k0 < K; k0 += 32) {
#pragma unroll
        for (int i0 = 0; i0 < 8; i0++) {
            int i = tid + (i0 << 8);
            int rr = i >> 5, kk = i & 31;
            int gr = rblk + rr, gk = k0 + kk;
            Wt[kk][rr] = (gr < R && gk < K) ? __ldg(&W[(size_t)gr * ws + gk]) : 0.f;
            int gs = sblk + rr;
            Xt[kk][rr] = (gs < S && gk < K) ? __ldg(&X[(size_t)gs * xs + gk]) : 0.f;
        }
        __syncthreads();
#pragma unroll
        for (int k = 0; k < 32; k++) {
            float4 w = *(const float4*)&Wt[k][tx << 2];
            float4 xv = *(const float4*)&Xt[k][ty << 2];
            acc[0][0] += xv.x * w.x; acc[0][1] += xv.x * w.y; acc[0][2] += xv.x * w.z; acc[0][3] += xv.x * w.w;
            acc[1][0] += xv.y * w.x; acc[1][1] += xv.y * w.y; acc[1][2] += xv.y * w.z; acc[1][3] += xv.y * w.w;
            acc[2][0] += xv.z * w.x; acc[2][1] += xv.z * w.y; acc[2][2] += xv.z * w.z; acc[2][3] += xv.z * w.w;
            acc[3][0] += xv.w * w.x; acc[3][1] += xv.w * w.y; acc[3][2] += xv.w * w.z; acc[3][3] += xv.w * w.w;
        }
        __syncthreads();
    }
#pragma unroll
    for (int j = 0; j < 4; j++) {
        int s = s0 + j;
        if (s >= S) continue;
#pragma unroll
        for (int i = 0; i < 4; i++) {
            int r = r0 + i;
            if (r >= R) continue;
            float v = acc[j][i] + b1[r] + b2[r];
            if (act) v = 1.f / (1.f + expf(-v));
            out[(size_t)s * os + r] = v;
        }
    }
}

// ------------------- 128x128x32 tiled GEMM, 8x8 microtile --------------------
__global__ __launch_bounds__(256)
void k_gemm128(const float* __restrict__ X, int xs,
               const float* __restrict__ W, int ws,
               const float* __restrict__ b1, const float* __restrict__ b2,
               float* __restrict__ out, int os,
               int S, int R, int K, int act) {
    __shared__ float Wt[32][132];
    __shared__ float Xt[32][132];
    const int tid = threadIdx.x;
    const int tx = tid & 15, ty = tid >> 4;
    const int rblk = blockIdx.x << 7, sblk = blockIdx.y << 7;
    float acc[8][8];
#pragma unroll
    for (int j = 0; j < 8; j++)
#pragma unroll
        for (int i = 0; i < 8; i++) acc[j][i] = 0.f;

    for (int k0 = 0; k0 < K; k0 += 32) {
        // load 128x32 of W and X (k-fast: coalesced 128B lines per row)
#pragma unroll
        for (int i0 = 0; i0 < 16; i0++) {
            int i = tid + (i0 << 8);
            int rr = i >> 5, kk = i & 31;
            int gr = rblk + rr, gk = k0 + kk;
            Wt[kk][rr] = (gr < R && gk < K) ? __ldg(&W[(size_t)gr * ws + gk]) : 0.f;
            int gs = sblk + rr;
            Xt[kk][rr] = (gs < S && gk < K) ? __ldg(&X[(size_t)gs * xs + gk]) : 0.f;
        }
        __syncthreads();
#pragma unroll 8
        for (int k = 0; k < 32; k++) {
            float4 w0 = *(const float4*)&Wt[k][tx << 3];
            float4 w1 = *(const float4*)&Wt[k][(tx << 3) + 4];
            float4 x0 = *(const float4*)&Xt[k][ty << 3];
            float4 x1 = *(const float4*)&Xt[k][(ty << 3) + 4];
            float wr[8] = {w0.x, w0.y, w0.z, w0.w, w1.x, w1.y, w1.z, w1.w};
            float xr[8] = {x0.x, x0.y, x0.z, x0.w, x1.x, x1.y, x1.z, x1.w};
#pragma unroll
            for (int j = 0; j < 8; j++)
#pragma unroll
                for (int i = 0; i < 8; i++) acc[j][i] += xr[j] * wr[i];
        }
        __syncthreads();
    }
#pragma unroll
    for (int j = 0; j < 8; j++) {
        int s = sblk + (ty << 3) + j;
        if (s >= S) continue;
#pragma unroll
        for (int i = 0; i < 8; i++) {
            int r = rblk + (tx << 3) + i;
            if (r >= R) continue;
            float v = acc[j][i] + b1[r] + b2[r];
            if (act) v = 1.f / (1.f + expf(-v));
            out[(size_t)s * os + r] = v;
        }
    }
}

// ------------------------------ persistent LSTM recurrence ------------------
// Whh rows for this block's hidden units live in SMEM as fp16, permuted into
// uint4 slots matched to the h float4 register layout (conflict-free LDS.128
// for both). fp32 accumulation. Double-buffered global h; ONE grid barrier per
// step: read g_hbuf[s&1], compute, write g_hbuf[(s+1)&1], barrier.
__global__ __launch_bounds__(256)
void k_lstm_recur(const float* __restrict__ pre,
                  const float* __restrict__ Whh,
                  float* __restrict__ hseq,
                  int S, int hid, unsigned nb) {
    extern __shared__ char smraw[];
    uint4* Wsm = (uint4*)smraw;                         // UPB*4 rows x 128 uint4
    float* hsm = (float*)(smraw + UPB * 4 * 128 * 16);  // 1024 floats
    float* gsm = hsm + 1024;                            // UPB*4
    float* csm = gsm + UPB * 4;                         // UPB

    const int tid = threadIdx.x;
    const int u0 = blockIdx.x * UPB;
    int nu = hid - u0;
    if (nu > UPB) nu = UPB;
    if (nu < 0) nu = 0;
    const int nrows = nu * 4;
    const int R4 = 4 * hid;

    // Fill Wsm: slot (rl*128 + jw*32 + l) holds fp16 weights for h positions
    //   base1 = 4*l + 256*jw (4 floats) and base2 = base1 + 128 (4 floats),
    // matching hreg[2jw] / hreg[2jw+1] = hsm4[l + 32*(2jw[+1])].
    for (int idx = tid; idx < nrows * 128; idx += 256) {
        int rl = idx >> 7, slot = idx & 127;
        int jw = slot >> 5, l = slot & 31;
        int ul = rl >> 2, gate = rl & 3;
        const float* wrow = Whh + (size_t)(gate * hid + u0 + ul) * hid;
        int base1 = 4 * l + 256 * jw;
        int base2 = base1 + 128;
        float w0 = (base1 + 0 < hid) ? __ldg(&wrow[base1 + 0]) : 0.f;
        float w1 = (base1 + 1 < hid) ? __ldg(&wrow[base1 + 1]) : 0.f;
        float w2 = (base1 + 2 < hid) ? __ldg(&wrow[base1 + 2]) : 0.f;
        float w3 = (base1 + 3 < hid) ? __ldg(&wrow[base1 + 3]) : 0.f;
        float w4 = (base2 + 0 < hid) ? __ldg(&wrow[base2 + 0]) : 0.f;
        float w5 = (base2 + 1 < hid) ? __ldg(&wrow[base2 + 1]) : 0.f;
        float w6 = (base2 + 2 < hid) ? __ldg(&wrow[base2 + 2]) : 0.f;
        float w7 = (base2 + 3 < hid) ? __ldg(&wrow[base2 + 3]) : 0.f;
        uint4 v;
        v.x = pack_h2(w0, w1);
        v.y = pack_h2(w2, w3);
        v.z = pack_h2(w4, w5);
        v.w = pack_h2(w6, w7);
        Wsm[idx] = v;
    }
    if (tid < nu) csm[tid] = 0.f;
    // zero both h buffers (block 0 covers the padded tail; owners cover units)
    if (tid < nu) {
        __stcg(&g_hbuf[0][u0 + tid], 0.f);
        __stcg(&g_hbuf[1][u0 + tid], 0.f);
    }
    if (blockIdx.x == 0) {
        for (int k = hid + tid; k < 1024; k += 256) {
            __stcg(&g_hbuf[0][k], 0.f);
            __stcg(&g_hbuf[1][k], 0.f);
        }
    }
    grid_barrier(nb);

    const int lane = tid & 31, warp = tid >> 5;
    for (int s = 0; s < S; s++) {
        const float* hin = g_hbuf[s & 1];
        float* hout = g_hbuf[(s + 1) & 1];
        // stage h (L2-fresh) into SMEM, then into registers per lane
        ((float4*)hsm)[tid] = __ldcg(((const float4*)hin) + tid);
        __syncthreads();
        const float4* hsm4 = (const float4*)hsm;
        float4 hreg[8];
#pragma unroll
        for (int i = 0; i < 8; i++) hreg[i] = hsm4[lane + (i << 5)];

        for (int rl = warp; rl < nrows; rl += 8) {
            int ul = rl >> 2, gate = rl & 3;
            float pv = 0.f;
            if (lane == 0) pv = __ldg(&pre[(size_t)s * R4 + gate * hid + u0 + ul]);
            const uint4* w4 = Wsm + rl * 128;
            float a = 0.f;
#pragma unroll
            for (int jw = 0; jw < 4; jw++) {
                uint4 w = w4[(jw << 5) + lane];
                float4 ha = hreg[2 * jw];
                float4 hb = hreg[2 * jw + 1];
                float2 f;
                f = __half22float2(*reinterpret_cast<const __half2*>(&w.x));
                a += f.x * ha.x + f.y * ha.y;
                f = __half22float2(*reinterpret_cast<const __half2*>(&w.y));
                a += f.x * ha.z + f.y * ha.w;
                f = __half22float2(*reinterpret_cast<const __half2*>(&w.z));
                a += f.x * hb.x + f.y * hb.y;
                f = __half22float2(*reinterpret_cast<const __half2*>(&w.w));
                a += f.x * hb.z + f.y * hb.w;
            }
#pragma unroll
            for (int off = 16; off; off >>= 1) a += __shfl_down_sync(0xffffffffu, a, off);
            if (lane == 0) gsm[rl] = a + pv;
        }
        __syncthreads();
        if (tid < nu) {
            float gi = gsm[tid * 4 + 0];
            float gf = gsm[tid * 4 + 1];
            float gg = gsm[tid * 4 + 2];
            float go = gsm[tid * 4 + 3];
            float c = sigf(gf) * csm[tid] + sigf(gi) * tanhf(gg);
            csm[tid] = c;
            float h = sigf(go) * tanhf(c);
            __stcg(&hout[u0 + tid], h);
            hseq[(size_t)s * 1024 + u0 + tid] = h;
        }
        grid_barrier(nb);
    }
}

// ------------------------------ host orchestration --------------------------

static void run_gemm(const float* X, int xs, const float* W, int ws,
                     const float* b1, const float* b2,
                     float* out, int os, int S, int R, int K, int act) {
    if (S >= 128) {
        dim3 g((R + 127) / 128, (S + 127) / 128);
        k_gemm128<<<g, 256>>>(X, xs, W, ws, b1, b2, out, os, S, R, K, act);
    } else {
        dim3 g((R + 63) / 64, (S + 63) / 64);
        k_gemm64<<<g, 256>>>(X, xs, W, ws, b1, b2, out, os, S, R, K, act);
    }
}

extern "C" void kernel_launch(void* const* d_in, const int* in_sizes, int n_in,
                              void* d_out, int out_size) {
    const float* vis      = (const float*)d_in[0];
    const int*   lang     = (const int*)d_in[1];
    const float* emb      = (const float*)d_in[2];
    const float* lWih     = (const float*)d_in[3];   // (2, 4000, 1000)
    const float* lWhh     = (const float*)d_in[4];   // (2, 4000, 1000)
    const float* lbih     = (const float*)d_in[5];   // (2, 4000)
    const float* lbhh     = (const float*)d_in[6];
    const float* mWih0    = (const float*)d_in[7];   // (4020, 1000)
    const float* mWihR    = (const float*)d_in[8];   // (2, 4020, 1005)
    const float* mWhh     = (const float*)d_in[9];   // (3, 4020, 1005)
    const float* mbih     = (const float*)d_in[10];  // (3, 4020)
    const float* mbhh     = (const float*)d_in[11];
    const float* afW      = (const float*)d_in[12];  // (2690, 1000)
    const float* afb      = (const float*)d_in[13];
    const float* ccW      = (const float*)d_in[14];  // (1000, 4691)
    const float* ccb      = (const float*)d_in[15];
    const float* ocW      = (const float*)d_in[16];  // (1, 1005)
    const float* ocb      = (const float*)d_in[17];
    float* out = (float*)d_out;

    float *p_le, *p_prel, *p_h1l, *p_lo, *p_filt, *p_vxT, *p_p, *p_ppart, *p_lelo;
    float *p_A, *p_Bt, *p_xseq, *p_prem, *p_hA, *p_hB, *p_zero;
    cudaGetSymbolAddress((void**)&p_le,    g_le);
    cudaGetSymbolAddress((void**)&p_prel,  g_prelang);
    cudaGetSymbolAddress((void**)&p_h1l,   g_h1l);
    cudaGetSymbolAddress((void**)&p_lo,    g_lo);
    cudaGetSymbolAddress((void**)&p_filt,  g_filt);
    cudaGetSymbolAddress((void**)&p_vxT,   g_vxT);
    cudaGetSymbolAddress((void**)&p_p,     g_p);
    cudaGetSymbolAddress((void**)&p_ppart, g_ppart);
    cudaGetSymbolAddress((void**)&p_lelo,  g_lelo);
    cudaGetSymbolAddress((void**)&p_A,     g_A);
    cudaGetSymbolAddress((void**)&p_Bt,    g_Bt);
    cudaGetSymbolAddress((void**)&p_xseq,  g_xseq);
    cudaGetSymbolAddress((void**)&p_prem,  g_prem);
    cudaGetSymbolAddress((void**)&p_hA,    g_hA);
    cudaGetSymbolAddress((void**)&p_hB,    g_hB);
    cudaGetSymbolAddress((void**)&p_zero,  g_zero);

    size_t recur_smem = (size_t)UPB * 4 * 128 * 16      // fp16 weights (uint4)
                      + 1024 * 4                         // hsm
                      + (UPB * 4 + UPB) * 4;             // gsm + csm
    cudaFuncSetAttribute(k_lstm_recur, cudaFuncAttributeMaxDynamicSharedMemorySize,
                         (int)recur_smem);

    // ---- language LSTM (2 layers, T=8, hid=1000) ----
    k_embed<<<8, 256>>>(emb, lang, p_le);
    run_gemm(p_le, 1000, lWih, 1000, lbih, lbhh, p_prel, 4000, 8, 4000, 1000, 0);
    k_lstm_recur<<<NB_RECUR, 256, recur_smem>>>(p_prel, lWhh, p_h1l, 8, 1000, NB_RECUR);
    run_gemm(p_h1l, 1024, lWih + 4000 * 1000, 1000, lbih + 4000, lbhh + 4000,
             p_prel, 4000, 8, 4000, 1000, 0);
    k_lstm_recur<<<NB_RECUR, 256, recur_smem>>>(p_prel, lWhh + 4000 * 1000, p_lo, 8, 1000, NB_RECUR);

    // ---- attention filter + p ----
    run_gemm(p_lo, 1024, afW, 1000, afb, p_zero, p_filt, 2690, 8, 2690, 1000, 1);
    k_visxyT<<<2690, 256>>>(vis, p_vxT);
    {
        dim3 gp(8, 8);
        k_p_part<<<gp, 256>>>(p_filt, vis, p_ppart);
        k_p_reduce<<<8, 256>>>(p_ppart, p_filt, p_p);
    }

    // ---- stage C decomposition:  q = A[hw] + Bt[t] + ccp * p[t,hw] ----
    k_lelo<<<8, 256>>>(p_le, p_lo, p_lelo);
    run_gemm(p_lelo, 2000, ccW + 2690, 4691, ccb, p_zero, p_Bt, 1000, 8, 1000, 2000, 0);
    run_gemm(p_vxT, 2720, ccW, 4691, p_zero, p_zero, p_A, 1000, 256, 1000, 2690, 0);
    k_xseq<<<2048, 256>>>(p_A, p_Bt, p_p, ccW, p_xseq);

    // ---- mRNN: 3 LSTM layers, seq 2048, hid 1005 ----
    run_gemm(p_xseq, 1024, mWih0, 1000, mbih, mbhh, p_prem, 4020, 2048, 4020, 1000, 0);
    k_lstm_recur<<<NB_RECUR, 256, recur_smem>>>(p_prem, mWhh, p_hA, 2048, 1005, NB_RECUR);

    run_gemm(p_hA, 1024, mWihR, 1005, mbih + 4020, mbhh + 4020, p_prem, 4020, 2048, 4020, 1005, 0);
    k_lstm_recur<<<NB_RECUR, 256, recur_smem>>>(p_prem, mWhh + (size_t)4020 * 1005, p_hB,
                                                2048, 1005, NB_RECUR);

    run_gemm(p_hB, 1024, mWihR + (size_t)4020 * 1005, 1005, mbih + 8040, mbhh + 8040,
             p_prem, 4020, 2048, 4020, 1005, 0);
    k_lstm_recur<<<NB_RECUR, 256, recur_smem>>>(p_prem, mWhh + (size_t)2 * 4020 * 1005, p_hA,
                                                2048, 1005, NB_RECUR);

    // ---- output projection ----
    k_final<<<256, 256>>>(p_hA, ocW, ocb, out);
}